// round 3
// baseline (speedup 1.0000x reference)
#include <cuda_runtime.h>

// ============================================================================
// Fused 3-layer MLP + rational-quadratic spline flow.
//   h1 = relu(x1 @ W1 + b1)            [B,32]@[32,256]
//   h2 = relu(h1 @ W2 + b2)            [B,256]@[256,256]
//   params = h2 @ W3 + b3              [B,256]@[256,1568]  (= 32 dims x 49)
//   (z2, log_det_sum) = RQ-spline(x2, params)
// One CTA = 128 rows. Everything stays in SMEM; params never touch HBM.
// Inner loops use packed fma.rn.f32x2 (2x fp32 FMA throughput on sm_103a).
// ============================================================================

typedef unsigned long long u64;

__device__ __forceinline__ u64 fma2(u64 a, u64 b, u64 c) {
    u64 d;
    asm("fma.rn.f32x2 %0, %1, %2, %3;" : "=l"(d) : "l"(a), "l"(b), "l"(c));
    return d;
}
__device__ __forceinline__ u64 pack2(float lo, float hi) {
    u64 r;
    asm("mov.b64 %0, {%1, %2};" : "=l"(r) : "f"(lo), "f"(hi));
    return r;
}
__device__ __forceinline__ void unpack2(u64 a, float& lo, float& hi) {
    asm("mov.b64 {%0, %1}, %2;" : "=f"(lo), "=f"(hi) : "l"(a));
}

union F4U { float4 f; ulonglong2 u; };

// ---- problem constants ----
#define NBINS  16
#define TAILC  3.0f
#define MINV   0.001f
#define EPSV   1e-6f
#define D1     32
#define D2     32
#define DFF    256
#define PPD    49          // params per dim (16 w + 16 h + 17 d)
#define DOUT   1568        // 32 * 49
#define TB     128         // rows per CTA
#define NTHR   256

// ---- shared memory layout (float offsets) ----
// persistent:  sH2t[256][132]  (h2 transposed: [feature][row], pad 132)
// phase A:     x1t[32][36] + sH1t[256][36]          (overlaid with phase B)
// phase B:     sW3[256][49] + sP[128][49]
// persistent:  sX2[128][33]
#define H2T_STRIDE 132
#define OFF_H2T    0
#define OFF_X1T    (DFF * H2T_STRIDE)                 // 33792
#define OFF_H1T    (OFF_X1T + D1 * 36)                // 34944
#define OFF_W3     (DFF * H2T_STRIDE)                 // 33792 (overlays X1T/H1T)
#define OFF_P      (OFF_W3 + DFF * PPD)               // 46336
#define OFF_X2     (OFF_P + TB * PPD)                 // 52608
#define SMEM_FLOATS (OFF_X2 + TB * 33)                // 56832
#define SMEM_BYTES  (SMEM_FLOATS * 4)                 // 227328 B  (< 232448 cap)

// Dense layer (K x 256 weights) for a 32-row subtile, output feature j = tid.
// srcT: smem [K][36] transposed activations; dstCol: &dst[j*stride + colbase].
template<int K>
__device__ __forceinline__ void dense_relu_32rows(
    const float* __restrict__ W, const float* __restrict__ bias,
    const float* __restrict__ srcT, float* __restrict__ dstCol, int j)
{
    u64 acc[16];
#pragma unroll
    for (int i = 0; i < 16; i++) acc[i] = 0ull;   // bits of (+0.f,+0.f)

#pragma unroll 4
    for (int k = 0; k < K; k++) {
        float w = W[k * DFF + j];                 // coalesced across lanes
        u64 wp = pack2(w, w);
        const float4* hp = reinterpret_cast<const float4*>(srcT + k * 36);
#pragma unroll
        for (int q = 0; q < 8; q++) {
            F4U v; v.f = hp[q];                   // broadcast LDS.128
            acc[2 * q]     = fma2(v.u.x, wp, acc[2 * q]);
            acc[2 * q + 1] = fma2(v.u.y, wp, acc[2 * q + 1]);
        }
    }
    float b = bias[j];
#pragma unroll
    for (int q = 0; q < 8; q++) {
        float a0, a1, a2, a3;
        unpack2(acc[2 * q], a0, a1);
        unpack2(acc[2 * q + 1], a2, a3);
        float4 o = make_float4(fmaxf(a0 + b, 0.f), fmaxf(a1 + b, 0.f),
                               fmaxf(a2 + b, 0.f), fmaxf(a3 + b, 0.f));
        reinterpret_cast<float4*>(dstCol)[q] = o;
    }
}

__device__ __forceinline__ float softplus_(float x) {
    // log(1+exp(x)) = max(x,0) + log(1+exp(-|x|))
    return fmaxf(x, 0.f) + __logf(1.f + __expf(-fabsf(x)));
}

__global__ void __launch_bounds__(NTHR, 1)
rq_fused_kernel(const float* __restrict__ x1, const float* __restrict__ x2,
                const float* __restrict__ W1, const float* __restrict__ b1,
                const float* __restrict__ W2, const float* __restrict__ b2,
                const float* __restrict__ W3, const float* __restrict__ b3,
                float* __restrict__ zOut, float* __restrict__ ldOut)
{
    extern __shared__ float sm[];
    const int tid = threadIdx.x;
    const int row0 = blockIdx.x * TB;

    // ---- preload x2 tile (persistent region) ----
    for (int idx = tid; idx < TB * D2; idx += NTHR) {
        int r = idx >> 5, c = idx & 31;
        sm[OFF_X2 + r * 33 + c] = x2[(size_t)(row0 + r) * D2 + c];
    }

    // ================= Phase A: build h2^T in SMEM (4 subtiles of 32 rows) ===
    for (int sub = 0; sub < 4; sub++) {
        const int rb = sub * 32;
        __syncthreads();  // prior readers of x1t/sH1t are done
        // x1 tile -> x1t[c][r]
        for (int idx = tid; idx < 32 * 32; idx += NTHR) {
            int r = idx >> 5, c = idx & 31;
            sm[OFF_X1T + c * 36 + r] = x1[(size_t)(row0 + rb + r) * D1 + c];
        }
        __syncthreads();
        // h1 = relu(x1@W1+b1) -> sH1t[j][0..31]
        dense_relu_32rows<D1>(W1, b1, sm + OFF_X1T, sm + OFF_H1T + tid * 36, tid);
        __syncthreads();
        // h2 = relu(h1@W2+b2) -> sH2t[j][rb..rb+31]
        dense_relu_32rows<DFF>(W2, b2, sm + OFF_H1T,
                               sm + OFF_H2T + tid * H2T_STRIDE + rb, tid);
    }
    __syncthreads();

    // ================= Phase B: per-dim params GEMM + spline epilogue ========
    const int pt = tid & 7;        // param-thread: params p = pt + 8*m (m<7, p<49)
    const int rt = tid >> 3;       // 32 row-threads, 4 rows each
    const int r0 = rt * 4;
    float ldacc = 0.f;

    for (int d = 0; d < D2; d++) {
        // stage W3 slice [256][49] into SMEM (read once per CTA per dim)
        for (int idx = tid; idx < DFF * PPD; idx += NTHR) {
            int k = idx / PPD;
            int p = idx - k * PPD;
            sm[OFF_W3 + idx] = W3[(size_t)k * DOUT + d * PPD + p];
        }
        __syncthreads();

        // GEMM: params[r0..r0+3][p] = sum_k h2t[k][r] * W3[k][p]
        u64 acc[7][2];
#pragma unroll
        for (int m = 0; m < 7; m++) { acc[m][0] = 0ull; acc[m][1] = 0ull; }

#pragma unroll 2
        for (int k = 0; k < DFF; k++) {
            F4U h;
            h.f = *reinterpret_cast<const float4*>(sm + OFF_H2T + k * H2T_STRIDE + r0);
            const float* wrow = sm + OFF_W3 + k * PPD;
#pragma unroll
            for (int m = 0; m < 7; m++) {
                int p = pt + 8 * m;
                if (p < PPD) {
                    float w = wrow[p];
                    u64 wp = pack2(w, w);
                    acc[m][0] = fma2(h.u.x, wp, acc[m][0]);
                    acc[m][1] = fma2(h.u.y, wp, acc[m][1]);
                }
            }
        }
        // bias + write params tile
#pragma unroll
        for (int m = 0; m < 7; m++) {
            int p = pt + 8 * m;
            if (p < PPD) {
                float b = b3[d * PPD + p];
                float a0, a1, a2, a3;
                unpack2(acc[m][0], a0, a1);
                unpack2(acc[m][1], a2, a3);
                sm[OFF_P + (r0 + 0) * PPD + p] = a0 + b;
                sm[OFF_P + (r0 + 1) * PPD + p] = a1 + b;
                sm[OFF_P + (r0 + 2) * PPD + p] = a2 + b;
                sm[OFF_P + (r0 + 3) * PPD + p] = a3 + b;
            }
        }
        __syncthreads();

        // ---- spline: one thread per row ----
        if (tid < TB) {
            const float* pp = sm + OFF_P + tid * PPD;
            float xv = sm[OFF_X2 + tid * 33 + d];

            float cumw[NBINS + 1], cumh[NBINS + 1];
            // widths softmax -> cumulative knots
            {
                float mx = pp[0];
#pragma unroll
                for (int i = 1; i < NBINS; i++) mx = fmaxf(mx, pp[i]);
                float e[NBINS]; float S = 0.f;
#pragma unroll
                for (int i = 0; i < NBINS; i++) { e[i] = __expf(pp[i] - mx); S += e[i]; }
                float c = (1.f - NBINS * MINV) / S;
                float run = 0.f;
                cumw[0] = -TAILC;
#pragma unroll
                for (int i = 0; i < NBINS; i++) {
                    run += MINV + c * e[i];
                    cumw[i + 1] = fmaf(2.f * TAILC, run, -TAILC);
                }
            }
            // heights
            {
                const float* ph = pp + NBINS;
                float mx = ph[0];
#pragma unroll
                for (int i = 1; i < NBINS; i++) mx = fmaxf(mx, ph[i]);
                float e[NBINS]; float S = 0.f;
#pragma unroll
                for (int i = 0; i < NBINS; i++) { e[i] = __expf(ph[i] - mx); S += e[i]; }
                float c = (1.f - NBINS * MINV) / S;
                float run = 0.f;
                cumh[0] = -TAILC;
#pragma unroll
                for (int i = 0; i < NBINS; i++) {
                    run += MINV + c * e[i];
                    cumh[i + 1] = fmaf(2.f * TAILC, run, -TAILC);
                }
            }

            bool inside = (xv >= -TAILC) && (xv <= TAILC);
            float xc = fminf(fmaxf(xv, -TAILC), TAILC);

            // idx = (#{m : ref[m] <= xc}) - 1 ; ref[0] = -TAIL always <= xc
            int idx = 0;
#pragma unroll
            for (int i = 1; i <= NBINS - 1; i++) idx += (cumw[i] <= xc) ? 1 : 0;
            idx += ((cumw[NBINS] + EPSV) <= xc) ? 1 : 0;
            if (idx > NBINS - 1) idx = NBINS - 1;

            float xk = cumw[idx];
            float xd = cumw[idx + 1] - xk;
            float yk = cumh[idx];
            float yd = cumh[idx + 1] - yk;
            float s  = yd / xd;
            float d0 = MINV + softplus_(pp[2 * NBINS + idx]);
            float d1 = MINV + softplus_(pp[2 * NBINS + idx + 1]);
            float xi = (xc - xk) / xd;
            float om = 1.f - xi;
            float xim = xi * om;
            float alpha = yd * (s * xi * xi + d0 * xim);
            float beta  = s + (d1 + d0 - 2.f * s) * xim;
            float z  = yk + alpha / beta;
            float dn = s * s * (d1 * xi * xi + 2.f * s * xim + d0 * om * om);
            float ld = __logf(dn) - 2.f * __logf(beta);

            zOut[(size_t)(row0 + tid) * D2 + d] = inside ? z : xv;
            ldacc += inside ? ld : 0.f;
        }
        __syncthreads();   // sP / sW3 reuse next dim
    }

    if (tid < TB) ldOut[row0 + tid] = ldacc;
}

extern "C" void kernel_launch(void* const* d_in, const int* in_sizes, int n_in,
                              void* d_out, int out_size)
{
    const float* x1 = (const float*)d_in[0];
    const float* x2 = (const float*)d_in[1];
    const float* W1 = (const float*)d_in[2];
    const float* b1 = (const float*)d_in[3];
    const float* W2 = (const float*)d_in[4];
    const float* b2 = (const float*)d_in[5];
    const float* W3 = (const float*)d_in[6];
    const float* b3 = (const float*)d_in[7];

    const int B = in_sizes[0] / D1;          // 65536
    float* zOut  = (float*)d_out;            // [B,32] then log_det_sum [B]
    float* ldOut = zOut + (size_t)B * D2;

    cudaFuncSetAttribute(rq_fused_kernel,
                         cudaFuncAttributeMaxDynamicSharedMemorySize, SMEM_BYTES);

    rq_fused_kernel<<<B / TB, NTHR, SMEM_BYTES>>>(x1, x2, W1, b1, W2, b2, W3, b3,
                                                  zOut, ldOut);
}

// round 11
// speedup vs baseline: 1.9798x; 1.9798x over previous
#include <cuda_runtime.h>
#include <cuda_bf16.h>

typedef unsigned long long u64;
typedef unsigned int u32;
typedef unsigned short u16;

// ============================================================================
// f32x2 packed FMA helpers (phase A)
// ============================================================================
__device__ __forceinline__ u64 fma2(u64 a, u64 b, u64 c) {
    u64 d; asm("fma.rn.f32x2 %0, %1, %2, %3;" : "=l"(d) : "l"(a), "l"(b), "l"(c)); return d;
}
__device__ __forceinline__ u64 pack2(float lo, float hi) {
    u64 r; asm("mov.b64 %0, {%1, %2};" : "=l"(r) : "f"(lo), "f"(hi)); return r;
}
__device__ __forceinline__ void unpack2(u64 a, float& lo, float& hi) {
    asm("mov.b64 {%0, %1}, %2;" : "=f"(lo), "=f"(hi) : "l"(a));
}
union F4U { float4 f; ulonglong2 u; };

__device__ __forceinline__ u32 smem_u32(const void* p) {
    u32 a;
    asm("{ .reg .u64 t; cvta.to.shared.u64 t, %1; cvt.u32.u64 %0, t; }"
        : "=r"(a) : "l"(p));
    return a;
}

// ============================================================================
// mma.sync / ldmatrix helpers (baseline PTX — compiles for compute_103)
// ============================================================================
__device__ __forceinline__ void ldsm4(u32* r, u32 a) {
    asm volatile("ldmatrix.sync.aligned.m8n8.x4.shared.b16 {%0,%1,%2,%3}, [%4];"
        : "=r"(r[0]), "=r"(r[1]), "=r"(r[2]), "=r"(r[3]) : "r"(a));
}
__device__ __forceinline__ void ldsm2(u32* r, u32 a) {
    asm volatile("ldmatrix.sync.aligned.m8n8.x2.shared.b16 {%0,%1}, [%2];"
        : "=r"(r[0]), "=r"(r[1]) : "r"(a));
}
__device__ __forceinline__ void mma16816(float* c, const u32* a, const u32* b) {
    asm volatile("mma.sync.aligned.m16n8k16.row.col.f32.bf16.bf16.f32 "
        "{%0,%1,%2,%3}, {%4,%5,%6,%7}, {%8,%9}, {%0,%1,%2,%3};"
        : "+f"(c[0]), "+f"(c[1]), "+f"(c[2]), "+f"(c[3])
        : "r"(a[0]), "r"(a[1]), "r"(a[2]), "r"(a[3]), "r"(b[0]), "r"(b[1]));
}

// ============================================================================
// Problem constants
// ============================================================================
#define NBINS  16
#define TAILC  3.0f
#define MINV   0.001f
#define EPSV   1e-6f
#define D1     32
#define D2     32
#define DFF    256
#define PPD    49
#define DOUT   1568
#define TB     128
#define NTHR   256

// ---- SMEM layout (bytes) ----
// A planes: h2 as bf16 hi/lo, [128 rows][256 k] with 528B row stride (ldmatrix
// conflict-free: 528/4 = 132 == 4 mod 32 -> 8 rows rotate through all banks).
#define ASTRIDE   528
#define SMB_AHI   0                       // 128*528 = 67584
#define SMB_ALO   67584                   // 67584        -> 135168
// B planes: W3 dim-slice transposed [56 params][256 k] bf16 hi/lo, 528B stride
#define SMB_BHI   135168                  // 56*528 = 29568
#define SMB_BLO   164736                  // 29568        -> 194304
// params tile [128][58] fp32
#define PARSTR    58
#define SMB_PAR   194304                  // 128*58*4 = 29696 -> 224000
// phase A scratch overlays the B region (only used before phase B)
#define SMB_X1T   135168                  // 32*36*4  = 4608
#define SMB_H1T   139776                  // 256*36*4 = 36864 (ends 176640 < 194304)
#define SMEM_BYTES 224000

// ============================================================================
// Phase A stage-1: 32 rows, output feature j = tid, fp32 -> H1T
// ============================================================================
template<int K>
__device__ __forceinline__ void dense_relu_32rows(
    const float* __restrict__ W, const float* __restrict__ bias,
    const float* __restrict__ srcT, float* __restrict__ dstCol, int j)
{
    u64 acc[16];
#pragma unroll
    for (int i = 0; i < 16; i++) acc[i] = 0ull;
#pragma unroll 4
    for (int k = 0; k < K; k++) {
        float w = W[k * DFF + j];
        u64 wp = pack2(w, w);
        const float4* hp = reinterpret_cast<const float4*>(srcT + k * 36);
#pragma unroll
        for (int q = 0; q < 8; q++) {
            F4U v; v.f = hp[q];
            acc[2 * q]     = fma2(v.u.x, wp, acc[2 * q]);
            acc[2 * q + 1] = fma2(v.u.y, wp, acc[2 * q + 1]);
        }
    }
    float b = bias[j];
#pragma unroll
    for (int q = 0; q < 8; q++) {
        float a0, a1, a2, a3;
        unpack2(acc[2 * q], a0, a1);
        unpack2(acc[2 * q + 1], a2, a3);
        float4 o = make_float4(fmaxf(a0 + b, 0.f), fmaxf(a1 + b, 0.f),
                               fmaxf(a2 + b, 0.f), fmaxf(a3 + b, 0.f));
        reinterpret_cast<float4*>(dstCol)[q] = o;
    }
}

// Phase A stage-2: same GEMM, but epilogue splits h2 -> bf16 hi/lo into A planes.
__device__ __forceinline__ void dense2_split_store(
    const float* __restrict__ W2, const float* __restrict__ b2,
    const float* __restrict__ H1T, char* smem, int rb, int j)
{
    u64 acc[16];
#pragma unroll
    for (int i = 0; i < 16; i++) acc[i] = 0ull;
#pragma unroll 4
    for (int k = 0; k < DFF; k++) {
        float w = W2[k * DFF + j];
        u64 wp = pack2(w, w);
        const float4* hp = reinterpret_cast<const float4*>(H1T + k * 36);
#pragma unroll
        for (int q = 0; q < 8; q++) {
            F4U v; v.f = hp[q];
            acc[2 * q]     = fma2(v.u.x, wp, acc[2 * q]);
            acc[2 * q + 1] = fma2(v.u.y, wp, acc[2 * q + 1]);
        }
    }
    float b = b2[j];
#pragma unroll
    for (int q = 0; q < 8; q++) {
        float v4[4];
        unpack2(acc[2 * q], v4[0], v4[1]);
        unpack2(acc[2 * q + 1], v4[2], v4[3]);
#pragma unroll
        for (int i = 0; i < 4; i++) {
            float v = fmaxf(v4[i] + b, 0.f);
            __nv_bfloat16 h = __float2bfloat16(v);
            __nv_bfloat16 l = __float2bfloat16(v - __bfloat162float(h));
            int row = rb + 4 * q + i;
            *reinterpret_cast<u16*>(smem + SMB_AHI + row * ASTRIDE + j * 2) =
                __bfloat16_as_ushort(h);
            *reinterpret_cast<u16*>(smem + SMB_ALO + row * ASTRIDE + j * 2) =
                __bfloat16_as_ushort(l);
        }
    }
}

__device__ __forceinline__ float softplus_(float x) {
    return fmaxf(x, 0.f) + __logf(1.f + __expf(-fabsf(x)));
}

// ============================================================================
// Stage W3 dim-slice -> B planes (bf16 hi/lo, B^T layout [p][k]).
// t in [0, nthr); nthr is 256 (prologue) or 128 (overlapped with spline).
// ============================================================================
__device__ __forceinline__ void stage_b(
    const float* __restrict__ W3, int d, char* smem, int t, int nthr)
{
    const int p = t & 63;
    const int seg = t >> 6;
    const int nseg = nthr >> 6;       // 4 or 2
    const int chunk = 128 / nseg;     // 32 or 64
    if (p < PPD) {
        const float* g0 = W3 + (size_t)d * PPD + p;
        const int k2e = (seg + 1) * chunk;
#pragma unroll 4
        for (int k2 = seg * chunk; k2 < k2e; k2++) {
            float v0 = g0[(size_t)(2 * k2) * DOUT];
            float v1 = g0[(size_t)(2 * k2 + 1) * DOUT];
            __nv_bfloat16 h0 = __float2bfloat16(v0);
            __nv_bfloat16 h1 = __float2bfloat16(v1);
            __nv_bfloat16 l0 = __float2bfloat16(v0 - __bfloat162float(h0));
            __nv_bfloat16 l1 = __float2bfloat16(v1 - __bfloat162float(h1));
            u32 hw = (u32)__bfloat16_as_ushort(h0) | ((u32)__bfloat16_as_ushort(h1) << 16);
            u32 lw = (u32)__bfloat16_as_ushort(l0) | ((u32)__bfloat16_as_ushort(l1) << 16);
            u32 off = (u32)(p * ASTRIDE + k2 * 4);
            *reinterpret_cast<u32*>(smem + SMB_BHI + off) = hw;
            *reinterpret_cast<u32*>(smem + SMB_BLO + off) = lw;
        }
    }
}

// ============================================================================
// Main kernel
// ============================================================================
__global__ void __launch_bounds__(NTHR, 1)
rq_fused_mma(const float* __restrict__ x1, const float* __restrict__ x2,
             const float* __restrict__ W1, const float* __restrict__ b1,
             const float* __restrict__ W2, const float* __restrict__ b2,
             const float* __restrict__ W3, const float* __restrict__ b3,
             float* __restrict__ zOut, float* __restrict__ ldOut)
{
    extern __shared__ char smem[];
    float* smf = reinterpret_cast<float*>(smem);
    const u32 sb = smem_u32(smem);
    const int tid = threadIdx.x;
    const int w = tid >> 5;
    const int lane = tid & 31;
    const size_t row0 = (size_t)blockIdx.x * TB;

    // ===================== Phase A: h2 -> bf16 hi/lo A planes ===============
    float* X1T = smf + SMB_X1T / 4;
    float* H1T = smf + SMB_H1T / 4;
    for (int sub = 0; sub < 4; sub++) {
        const int rb = sub * 32;
        __syncthreads();
        for (int idx = tid; idx < 32 * 32; idx += NTHR) {
            int r = idx >> 5, c = idx & 31;
            X1T[c * 36 + r] = x1[(row0 + rb + r) * D1 + c];
        }
        __syncthreads();
        dense_relu_32rows<D1>(W1, b1, X1T, H1T + tid * 36, tid);
        __syncthreads();
        dense2_split_store(W2, b2, H1T, smem, rb, tid);
    }
    __syncthreads();

    // prologue: stage B(0) with all 256 threads
    stage_b(W3, 0, smem, tid, NTHR);
    __syncthreads();

    // lane decomposition for mma fragments
    const int g = lane >> 2, tig = lane & 3;
    const int at = lane >> 3, ar = lane & 7;
    const u32 aoff = (u32)((16 * w + (at & 1) * 8 + ar) * ASTRIDE + ((at >> 1) * 8) * 2);
    const u32 aHiBase = sb + SMB_AHI + aoff;
    const u32 aLoBase = sb + SMB_ALO + aoff;
    const int bt = (lane >> 3) & 1, br = lane & 7;

    float ldacc = 0.f;
    float* par = smf + SMB_PAR / 4;

    for (int d = 0; d < D2; d++) {
        // ---------------- MMA: params(d) = h2 @ W3_d (3-pass bf16) ----------
        float c[7][4];
#pragma unroll
        for (int nt = 0; nt < 7; nt++)
#pragma unroll
            for (int i = 0; i < 4; i++) c[nt][i] = 0.f;

        for (int ks = 0; ks < 16; ks++) {
            u32 ahi[4], alo[4];
            ldsm4(ahi, aHiBase + ks * 32);
            ldsm4(alo, aLoBase + ks * 32);
#pragma unroll
            for (int nt = 0; nt < 7; nt++) {
                u32 boff = (u32)((nt * 8 + br) * ASTRIDE + bt * 16 + ks * 32);
                u32 bhi[2], blo[2];
                ldsm2(bhi, sb + SMB_BHI + boff);
                ldsm2(blo, sb + SMB_BLO + boff);
                mma16816(c[nt], ahi, bhi);
                mma16816(c[nt], ahi, blo);
                mma16816(c[nt], alo, bhi);
            }
        }
        // write params (+bias) to SMEM
        const float* b3d = b3 + d * PPD;
#pragma unroll
        for (int nt = 0; nt < 7; nt++) {
            int col = nt * 8 + 2 * tig;
            float bb0 = 0.f, bb1 = 0.f;
            if (col < PPD)     bb0 = b3d[col];
            if (col + 1 < PPD) bb1 = b3d[col + 1];
            int rA = 16 * w + g;
            *reinterpret_cast<float2*>(par + rA * PARSTR + col) =
                make_float2(c[nt][0] + bb0, c[nt][1] + bb1);
            *reinterpret_cast<float2*>(par + (rA + 8) * PARSTR + col) =
                make_float2(c[nt][2] + bb0, c[nt][3] + bb1);
        }
        __syncthreads();

        // ------------- spline(d) on warps 0-3 | stage B(d+1) on 4-7 --------
        if (tid < TB) {
            const float* pp = par + tid * PARSTR;
            float xv = x2[(row0 + tid) * D2 + d];

            float cumw[NBINS + 1], cumh[NBINS + 1];
            {
                float mx = pp[0];
#pragma unroll
                for (int i = 1; i < NBINS; i++) mx = fmaxf(mx, pp[i]);
                float e[NBINS]; float S = 0.f;
#pragma unroll
                for (int i = 0; i < NBINS; i++) { e[i] = __expf(pp[i] - mx); S += e[i]; }
                float cs = (1.f - NBINS * MINV) / S;
                float run = 0.f;
                cumw[0] = -TAILC;
#pragma unroll
                for (int i = 0; i < NBINS; i++) {
                    run += MINV + cs * e[i];
                    cumw[i + 1] = fmaf(2.f * TAILC, run, -TAILC);
                }
            }
            {
                const float* ph = pp + NBINS;
                float mx = ph[0];
#pragma unroll
                for (int i = 1; i < NBINS; i++) mx = fmaxf(mx, ph[i]);
                float e[NBINS]; float S = 0.f;
#pragma unroll
                for (int i = 0; i < NBINS; i++) { e[i] = __expf(ph[i] - mx); S += e[i]; }
                float cs = (1.f - NBINS * MINV) / S;
                float run = 0.f;
                cumh[0] = -TAILC;
#pragma unroll
                for (int i = 0; i < NBINS; i++) {
                    run += MINV + cs * e[i];
                    cumh[i + 1] = fmaf(2.f * TAILC, run, -TAILC);
                }
            }

            bool inside = (xv >= -TAILC) && (xv <= TAILC);
            float xc = fminf(fmaxf(xv, -TAILC), TAILC);

            int idx = 0;
#pragma unroll
            for (int i = 1; i <= NBINS - 1; i++) idx += (cumw[i] <= xc) ? 1 : 0;
            idx += ((cumw[NBINS] + EPSV) <= xc) ? 1 : 0;
            if (idx > NBINS - 1) idx = NBINS - 1;

            float xk = cumw[idx];
            float xd = cumw[idx + 1] - xk;
            float yk = cumh[idx];
            float yd = cumh[idx + 1] - yk;
            float s  = yd / xd;
            float d0 = MINV + softplus_(pp[2 * NBINS + idx]);
            float d1v = MINV + softplus_(pp[2 * NBINS + idx + 1]);
            float xi = (xc - xk) / xd;
            float om = 1.f - xi;
            float xim = xi * om;
            float alpha = yd * (s * xi * xi + d0 * xim);
            float beta  = s + (d1v + d0 - 2.f * s) * xim;
            float z  = yk + alpha / beta;
            float dn = s * s * (d1v * xi * xi + 2.f * s * xim + d0 * om * om);
            float ld = __logf(dn) - 2.f * __logf(beta);

            zOut[(row0 + tid) * D2 + d] = inside ? z : xv;
            ldacc += inside ? ld : 0.f;
        } else if (d + 1 < D2) {
            stage_b(W3, d + 1, smem, tid - TB, TB);
        }
        __syncthreads();
    }

    if (tid < TB) ldOut[row0 + tid] = ldacc;
}

extern "C" void kernel_launch(void* const* d_in, const int* in_sizes, int n_in,
                              void* d_out, int out_size)
{
    const float* x1 = (const float*)d_in[0];
    const float* x2 = (const float*)d_in[1];
    const float* W1 = (const float*)d_in[2];
    const float* b1 = (const float*)d_in[3];
    const float* W2 = (const float*)d_in[4];
    const float* b2 = (const float*)d_in[5];
    const float* W3 = (const float*)d_in[6];
    const float* b3 = (const float*)d_in[7];

    const int B = in_sizes[0] / D1;
    float* zOut  = (float*)d_out;
    float* ldOut = zOut + (size_t)B * D2;

    cudaFuncSetAttribute(rq_fused_mma,
                         cudaFuncAttributeMaxDynamicSharedMemorySize, SMEM_BYTES);

    rq_fused_mma<<<B / TB, NTHR, SMEM_BYTES>>>(x1, x2, W1, b1, W2, b2, W3, b3,
                                               zOut, ldOut);
}